// round 10
// baseline (speedup 1.0000x reference)
#include <cuda_runtime.h>
#include <cuda_bf16.h>

// Problem constants
#define B_   8
#define T_   4096
#define E_   1024
#define H_   16
#define L_   64
#define HD_  64
#define NBLK (T_ / L_)        // 64 blocks per sequence
#define M_   (B_ * T_)        // 32768 rows
#define N1_  (3 * E_)         // 3072

// Scratch (static device allocations are allowed; cudaMalloc is not)
__device__ float g_qkv[(size_t)M_ * N1_];   // 402 MB: qkv projection output
__device__ float g_att[(size_t)M_ * E_];    // 134 MB: attention output

// ---------------------------------------------------------------------------
// SGEMM: C[M,N] = A[M,K] @ B[N,K]^T + bias[N]
// A row-major (K contiguous), B row-major (K contiguous) -> A*B^T
// 128x128 tile, BK=16, 256 threads, 8x8 microtile per thread.
// ---------------------------------------------------------------------------
__global__ __launch_bounds__(256, 2)
void sgemm_abt(const float* __restrict__ A, const float* __restrict__ Bm,
               const float* __restrict__ bias, float* __restrict__ C,
               int M, int N, int K)
{
    constexpr int BM = 128, BN = 128, BK = 16;
    __shared__ float As[BK][BM];
    __shared__ float Bs[BK][BN];

    const int tid = threadIdx.x;
    const int tx  = tid & 15;        // 0..15  (N direction)
    const int ty  = tid >> 4;        // 0..15  (M direction)

    const long mBase = (long)blockIdx.y * BM;
    const long nBase = (long)blockIdx.x * BN;

    const float* Ag = A  + mBase * K;
    const float* Bg = Bm + nBase * K;

    float acc[8][8];
#pragma unroll
    for (int i = 0; i < 8; i++)
#pragma unroll
        for (int j = 0; j < 8; j++) acc[i][j] = 0.0f;

    for (int k0 = 0; k0 < K; k0 += BK) {
        // Load 128x16 of A and B into smem (transposed to k-major).
        // 2048 floats each / 256 threads = 2 float4 per thread per matrix.
#pragma unroll
        for (int i = 0; i < 2; i++) {
            int idx = tid + i * 256;
            int row = idx >> 2;            // 0..127
            int kc  = (idx & 3) * 4;       // 0,4,8,12
            float4 a = *(const float4*)(Ag + (long)row * K + k0 + kc);
            As[kc + 0][row] = a.x; As[kc + 1][row] = a.y;
            As[kc + 2][row] = a.z; As[kc + 3][row] = a.w;
            float4 b = *(const float4*)(Bg + (long)row * K + k0 + kc);
            Bs[kc + 0][row] = b.x; Bs[kc + 1][row] = b.y;
            Bs[kc + 2][row] = b.z; Bs[kc + 3][row] = b.w;
        }
        __syncthreads();

#pragma unroll
        for (int kk = 0; kk < BK; kk++) {
            float4 a0 = *(const float4*)&As[kk][ty * 8];
            float4 a1 = *(const float4*)&As[kk][ty * 8 + 4];
            float4 b0 = *(const float4*)&Bs[kk][tx * 8];
            float4 b1 = *(const float4*)&Bs[kk][tx * 8 + 4];
            float a[8] = {a0.x, a0.y, a0.z, a0.w, a1.x, a1.y, a1.z, a1.w};
            float b[8] = {b0.x, b0.y, b0.z, b0.w, b1.x, b1.y, b1.z, b1.w};
#pragma unroll
            for (int i = 0; i < 8; i++)
#pragma unroll
                for (int j = 0; j < 8; j++)
                    acc[i][j] += a[i] * b[j];
        }
        __syncthreads();
    }

    // Epilogue: add bias, vectorized stores.
    float bfrag[8];
#pragma unroll
    for (int j = 0; j < 8; j++) bfrag[j] = bias[nBase + tx * 8 + j];

#pragma unroll
    for (int i = 0; i < 8; i++) {
        long m = mBase + ty * 8 + i;
        float* Cp = C + m * (long)N + nBase + tx * 8;
        float4 o0, o1;
        o0.x = acc[i][0] + bfrag[0]; o0.y = acc[i][1] + bfrag[1];
        o0.z = acc[i][2] + bfrag[2]; o0.w = acc[i][3] + bfrag[3];
        o1.x = acc[i][4] + bfrag[4]; o1.y = acc[i][5] + bfrag[5];
        o1.z = acc[i][6] + bfrag[6]; o1.w = acc[i][7] + bfrag[7];
        *(float4*)(Cp)     = o0;
        *(float4*)(Cp + 4) = o1;
    }
}

// ---------------------------------------------------------------------------
// Local block attention: one CTA per (b, h, n) block of 64 tokens.
// qkv buffer layout: [b*T + t][3E], q at +0, k at +E, v at +2E, head h at
// column h*HD. Computes softmax(scale * q @ k^T) @ v into g_att[(b*T+t)][E].
//
// SMEM (static, 33.3 KB): bufA = q (padded pitch 65) -> S -> P
//                         bufB = k^T (kt[d][l])      -> v (natural [m][d])
// Thread mapping for matmuls: l = tid/4 (row), columns (tid%4)*16 .. +15.
// ---------------------------------------------------------------------------
__global__ __launch_bounds__(256)
void local_attn(const float* __restrict__ qkv, float* __restrict__ out)
{
    __shared__ float bufA[L_][HD_ + 1];   // q / S / P, pitch 65 (conflict-free)
    __shared__ float bufB[L_][HD_ + 1];   // k^T, then v

    const int bid = blockIdx.x;
    const int n = bid % NBLK;
    const int h = (bid / NBLK) % H_;
    const int b = bid / (NBLK * H_);
    const int tid = threadIdx.x;

    const long rowBase = (long)b * T_ + (long)n * L_;
    const int l  = tid >> 2;             // 0..63
    const int c0 = (tid & 3) * 16;       // 0,16,32,48
    const float scale = 0.125f;          // HD^-0.5

    const float* qp = qkv + (rowBase + l) * (long)N1_ + h * HD_;

    // Load q (scaled) into bufA[l][d]; load k transposed into bufB[d][l].
#pragma unroll
    for (int j = 0; j < 16; j += 4) {
        float4 q4 = *(const float4*)(qp + c0 + j);
        bufA[l][c0 + j + 0] = q4.x * scale;
        bufA[l][c0 + j + 1] = q4.y * scale;
        bufA[l][c0 + j + 2] = q4.z * scale;
        bufA[l][c0 + j + 3] = q4.w * scale;
        float4 k4 = *(const float4*)(qp + E_ + c0 + j);
        bufB[c0 + j + 0][l] = k4.x;
        bufB[c0 + j + 1][l] = k4.y;
        bufB[c0 + j + 2][l] = k4.z;
        bufB[c0 + j + 3][l] = k4.w;
    }
    __syncthreads();

    // S[l][m] = sum_d q[l][d] * k[m][d], m = c0..c0+15, kept in registers.
    float s[16];
#pragma unroll
    for (int j = 0; j < 16; j++) s[j] = 0.0f;
    for (int d = 0; d < HD_; d++) {
        float qv = bufA[l][d];
#pragma unroll
        for (int j = 0; j < 16; j++)
            s[j] += qv * bufB[d][c0 + j];
    }
    __syncthreads();   // all reads of q (bufA) and k^T (bufB) complete

    // Write S into bufA; load v into bufB (natural [m][d] layout).
#pragma unroll
    for (int j = 0; j < 16; j++) bufA[l][c0 + j] = s[j];
#pragma unroll
    for (int j = 0; j < 16; j += 4) {
        float4 v4 = *(const float4*)(qp + 2 * E_ + c0 + j);
        bufB[l][c0 + j + 0] = v4.x;
        bufB[l][c0 + j + 1] = v4.y;
        bufB[l][c0 + j + 2] = v4.z;
        bufB[l][c0 + j + 3] = v4.w;
    }
    __syncthreads();

    // Row softmax: warp w handles rows w*8 .. w*8+7, lane covers 2 columns.
    const int wid = tid >> 5, lane = tid & 31;
#pragma unroll
    for (int rr = 0; rr < 8; rr++) {
        int r = wid * 8 + rr;
        float v0 = bufA[r][lane];
        float v1 = bufA[r][lane + 32];
        float mx = fmaxf(v0, v1);
#pragma unroll
        for (int o = 16; o > 0; o >>= 1)
            mx = fmaxf(mx, __shfl_xor_sync(0xffffffffu, mx, o));
        float e0 = __expf(v0 - mx);
        float e1 = __expf(v1 - mx);
        float sm = e0 + e1;
#pragma unroll
        for (int o = 16; o > 0; o >>= 1)
            sm += __shfl_xor_sync(0xffffffffu, sm, o);
        float inv = 1.0f / sm;
        bufA[r][lane]      = e0 * inv;
        bufA[r][lane + 32] = e1 * inv;
    }
    __syncthreads();

    // O[l][d] = sum_m P[l][m] * v[m][d], d = c0..c0+15.
    float o[16];
#pragma unroll
    for (int j = 0; j < 16; j++) o[j] = 0.0f;
    for (int m = 0; m < L_; m++) {
        float p = bufA[l][m];
#pragma unroll
        for (int j = 0; j < 16; j++)
            o[j] += p * bufB[m][c0 + j];
    }

    float* op = out + (rowBase + l) * (long)E_ + h * HD_ + c0;
#pragma unroll
    for (int j = 0; j < 16; j += 4) {
        float4 o4 = make_float4(o[j], o[j + 1], o[j + 2], o[j + 3]);
        *(float4*)(op + j) = o4;
    }
}

// ---------------------------------------------------------------------------
// Launch: QKV GEMM -> local attention -> output GEMM (default stream, serial)
// ---------------------------------------------------------------------------
extern "C" void kernel_launch(void* const* d_in, const int* in_sizes, int n_in,
                              void* d_out, int out_size)
{
    const float* x     = (const float*)d_in[0];   // (B,T,E)
    const float* Wqkv  = (const float*)d_in[1];   // (3E,E)
    const float* bqkv  = (const float*)d_in[2];   // (3E,)
    const float* Wout  = (const float*)d_in[3];   // (E,E)
    const float* bout  = (const float*)d_in[4];   // (E,)
    float* out = (float*)d_out;                   // (B,T,E)

    void* p;
    cudaGetSymbolAddress(&p, g_qkv);
    float* qkv = (float*)p;
    cudaGetSymbolAddress(&p, g_att);
    float* att = (float*)p;

    // GEMM1: qkv = x @ Wqkv^T + bqkv   (32768 x 3072 x 1024)
    sgemm_abt<<<dim3(N1_ / 128, M_ / 128), 256>>>(x, Wqkv, bqkv, qkv,
                                                  M_, N1_, E_);
    // Local block attention (8 * 16 * 64 = 8192 blocks)
    local_attn<<<B_ * H_ * NBLK, 256>>>(qkv, att);

    // GEMM2: out = att @ Wout^T + bout (32768 x 1024 x 1024)
    sgemm_abt<<<dim3(E_ / 128, M_ / 128), 256>>>(att, Wout, bout, out,
                                                 M_, E_, E_);
}